// round 9
// baseline (speedup 1.0000x reference)
#include <cuda_runtime.h>
#include <cuda_bf16.h>
#include <math.h>
#include <stdint.h>

// Problem dims (fixed)
#define NB   256
#define TT   128
#define DD   512
#define HH   1024
#define GG   4096
#define OUTD 128

typedef __nv_bfloat16 bf16;

// ---------------- device scratch ----------------
__device__ bf16 g_Wih_hi[GG * DD];
__device__ bf16 g_Wih_lo[GG * DD];
__device__ bf16 g_Whh_hi[GG * HH];
__device__ bf16 g_Whh_lo[GG * HH];
__device__ bf16 g_x_hi[(size_t)NB * TT * DD];
__device__ bf16 g_x_lo[(size_t)NB * TT * DD];
__device__ float g_bias_r[GG];
__device__ float g_xg[(size_t)TT * NB * GG];   // [t][batch][gate]
__device__ bf16 g_h_hi[2][NB * HH];
__device__ bf16 g_h_lo[2][NB * HH];
__device__ float g_hlast[NB * HH];
__device__ float g_cbuf[NB * HH];

// ---------------- low-level helpers ----------------
__device__ __forceinline__ uint32_t smem_u32(const void* p) {
    uint32_t a;
    asm("{ .reg .u64 t; cvta.to.shared.u64 t, %1; cvt.u32.u64 %0, t; }" : "=r"(a) : "l"(p));
    return a;
}
__device__ __forceinline__ void cp16(uint32_t dst, const void* src) {
    asm volatile("cp.async.cg.shared.global [%0], [%1], 16;"
                 :: "r"(dst), "l"(__cvta_generic_to_global(src)) : "memory");
}
#define CP_COMMIT() asm volatile("cp.async.commit_group;" ::: "memory")
#define CP_WAIT(n)  asm volatile("cp.async.wait_group %0;" :: "n"(n) : "memory")

__device__ __forceinline__ void ldsm4(uint32_t* r, uint32_t addr) {
    asm volatile("ldmatrix.sync.aligned.m8n8.x4.shared.b16 {%0,%1,%2,%3}, [%4];"
                 : "=r"(r[0]), "=r"(r[1]), "=r"(r[2]), "=r"(r[3]) : "r"(addr));
}
__device__ __forceinline__ void mma16816(float* d, const uint32_t* a, uint32_t b0, uint32_t b1) {
    asm volatile(
        "mma.sync.aligned.m16n8k16.row.col.f32.bf16.bf16.f32 "
        "{%0,%1,%2,%3}, {%4,%5,%6,%7}, {%8,%9}, {%0,%1,%2,%3};"
        : "+f"(d[0]), "+f"(d[1]), "+f"(d[2]), "+f"(d[3])
        : "r"(a[0]), "r"(a[1]), "r"(a[2]), "r"(a[3]), "r"(b0), "r"(b1));
}

// tile rows = 64 bf16 = 128B = 8 x 16B chunks; 8-way XOR swizzle within the row
__device__ __forceinline__ uint32_t swz(int row, int j) {
    return (uint32_t)(row * 128 + ((j ^ (row & 7)) << 4));
}

// ---------------- prep ----------------
__global__ void prep_kernel(const float* __restrict__ x,
                            const float* __restrict__ Wih,
                            const float* __restrict__ Whh,
                            const float* __restrict__ bih,
                            const float* __restrict__ bhh) {
    int idx = blockIdx.x * blockDim.x + threadIdx.x;
    int stride = gridDim.x * blockDim.x;
    for (int i = idx; i < GG * DD; i += stride) {
        int rn = i / DD, d = i - rn * DD;
        int q = rn >> 2, p = rn & 3;
        float w = Wih[(p * HH + q) * DD + d];
        bf16 hi = __float2bfloat16(w);
        g_Wih_hi[i] = hi;
        g_Wih_lo[i] = __float2bfloat16(w - __bfloat162float(hi));
    }
    for (int i = idx; i < GG * HH; i += stride) {
        int rn = i / HH, d = i - rn * HH;
        int q = rn >> 2, p = rn & 3;
        float w = Whh[(p * HH + q) * HH + d];
        bf16 hi = __float2bfloat16(w);
        g_Whh_hi[i] = hi;
        g_Whh_lo[i] = __float2bfloat16(w - __bfloat162float(hi));
    }
    for (size_t i = idx; i < (size_t)NB * TT * DD; i += stride) {
        float v = x[i];
        bf16 hi = __float2bfloat16(v);
        g_x_hi[i] = hi;
        g_x_lo[i] = __float2bfloat16(v - __bfloat162float(hi));
    }
    for (int i = idx; i < GG; i += stride) {
        int q = i >> 2, p = i & 3;
        g_bias_r[i] = bih[p * HH + q] + bhh[p * HH + q];
    }
    for (int i = idx; i < NB * HH; i += stride) {
        g_h_hi[0][i] = __float2bfloat16(0.0f);
        g_h_lo[0][i] = __float2bfloat16(0.0f);
        g_cbuf[i] = 0.0f;
    }
}

// ---------------- combined-pass multistage HMMA mainloop (512 threads) ----------------
// Per K-chunk (BK=64) load Ahi, Alo, Bhi, Blo ONCE; 3 MMA passes reuse frags.
// KG=1: 16 warps 4(M)x4(N), each does all 4 K-substeps (MF = BM/64).
// KG=2: 2 K-groups x 8 warps (2Mx4N), group g does K-substeps {2g, 2g+1}
//       into its OWN accumulators (MF = BM/32); caller sums the groups.
template <int BM, int MF, int KG, int S>
__device__ __forceinline__ void mma_mainloop(
    const bf16* __restrict__ Ahi, const bf16* __restrict__ Alo,
    const bf16* __restrict__ Bhi, const bf16* __restrict__ Blo,
    int K, int m0, int n0, uint32_t sbase, float acc[MF][4][4]) {
    constexpr int NT = 512;
    constexpr int ATILE = BM * 128;
    constexpr int BTILE = 128 * 128;
    constexpr int STAGE = 2 * ATILE + 2 * BTILE;
    constexpr int KSUB = 4 / KG;             // K-substeps per warp
    const int tid = threadIdx.x;
    const int lane = tid & 31, wid = tid >> 5;
    const int kg = (KG == 2) ? (wid >> 3) : 0;
    const int w8 = (KG == 2) ? (wid & 7) : wid;
    const int wm = (w8 >> 2) * (16 * MF);
    const int wn = (w8 & 3) * 32;
    const int KC = K / 64;

    auto load_chunk = [&](int kc, int buf) {
        uint32_t base = sbase + buf * STAGE;
#pragma unroll
        for (int i0 = 0; i0 < BM * 8; i0 += NT) {
            int i = i0 + tid;
            int row = i >> 3, j = i & 7;
            size_t goff = (size_t)(m0 + row) * K + kc * 64 + j * 8;
            uint32_t so = swz(row, j);
            cp16(base + so, Ahi + goff);
            cp16(base + ATILE + so, Alo + goff);
        }
#pragma unroll
        for (int i0 = 0; i0 < 1024; i0 += NT) {
            int i = i0 + tid;
            int row = i >> 3, j = i & 7;
            size_t goff = (size_t)(n0 + row) * K + kc * 64 + j * 8;
            uint32_t so = swz(row, j);
            cp16(base + 2 * ATILE + so, Bhi + goff);
            cp16(base + 2 * ATILE + BTILE + so, Blo + goff);
        }
        CP_COMMIT();
    };

    // prologue: stages 0..S-2 (caller's earlier cp.async joins group 0)
#pragma unroll
    for (int s = 0; s < S - 1; s++) load_chunk(s, s);

    int cbuf = 0;
    int lbuf = (S - 1) % S;
    for (int ci = 0; ci < KC; ci++) {
        CP_WAIT(S - 2);
        __syncthreads();
        if (ci + S - 1 < KC) load_chunk(ci + S - 1, lbuf);
        else CP_COMMIT();
        lbuf = (lbuf + 1 == S) ? 0 : lbuf + 1;
        uint32_t sAh = sbase + cbuf * STAGE;
        uint32_t sAl = sAh + ATILE;
        uint32_t sBh = sAh + 2 * ATILE;
        uint32_t sBl = sBh + BTILE;
        cbuf = (cbuf + 1 == S) ? 0 : cbuf + 1;
#pragma unroll
        for (int ks2 = 0; ks2 < KSUB; ks2++) {
            const int ks = kg * KSUB + ks2;
            uint32_t ah[MF][4], al[MF][4], bh[2][4], bl[2][4];
            const int j = ks * 2 + (lane >> 4);
#pragma unroll
            for (int mi = 0; mi < MF; mi++) {
                int row = wm + mi * 16 + (lane & 15);
                uint32_t so = swz(row, j);
                ldsm4(ah[mi], sAh + so);
                ldsm4(al[mi], sAl + so);
            }
#pragma unroll
            for (int bi = 0; bi < 2; bi++) {
                int row = wn + bi * 16 + (lane & 15);
                uint32_t so = swz(row, j);
                ldsm4(bh[bi], sBh + so);
                ldsm4(bl[bi], sBl + so);
            }
            // pass 0: Ahi * Bhi
#pragma unroll
            for (int mi = 0; mi < MF; mi++)
#pragma unroll
                for (int nf = 0; nf < 4; nf++)
                    mma16816(acc[mi][nf], ah[mi], bh[nf >> 1][nf & 1], bh[nf >> 1][(nf & 1) + 2]);
            // pass 1: Ahi * Blo
#pragma unroll
            for (int mi = 0; mi < MF; mi++)
#pragma unroll
                for (int nf = 0; nf < 4; nf++)
                    mma16816(acc[mi][nf], ah[mi], bl[nf >> 1][nf & 1], bl[nf >> 1][(nf & 1) + 2]);
            // pass 2: Alo * Bhi
#pragma unroll
            for (int mi = 0; mi < MF; mi++)
#pragma unroll
                for (int nf = 0; nf < 4; nf++)
                    mma16816(acc[mi][nf], al[mi], bh[nf >> 1][nf & 1], bh[nf >> 1][(nf & 1) + 2]);
        }
    }
    __syncthreads();   // protect stage buffers before epilogue reuse
}

// ---------------- xgates: writes transposed g_xg[t][batch][gate] ----------------
// KG=1, BM=128, MF=2 (warp tile 32x32), stage=64KB, S=3 -> 192KB, 512 threads
#define XG_SMEM (3 * (2 * 128 * 128 + 2 * 128 * 128))

__global__ __launch_bounds__(512, 1)
void xgates_mma_kernel() {
    extern __shared__ __align__(1024) char smem[];
    const uint32_t sbase = smem_u32(smem);
    const int bn = blockIdx.x, bm = blockIdx.y;
    const int tid = threadIdx.x, lane = tid & 31, wid = tid >> 5;
    const int wm = (wid >> 2) * 32, wn = (wid & 3) * 32;

    float acc[2][4][4];
#pragma unroll
    for (int i = 0; i < 2; i++)
#pragma unroll
        for (int j = 0; j < 4; j++)
#pragma unroll
            for (int k = 0; k < 4; k++) acc[i][j][k] = 0.0f;

    mma_mainloop<128, 2, 1, 3>(g_x_hi, g_x_lo, g_Wih_hi, g_Wih_lo, DD,
                               bm * 128, bn * 128, sbase, acc);

#pragma unroll
    for (int mi = 0; mi < 2; mi++) {
#pragma unroll
        for (int nf = 0; nf < 4; nf++) {
            int m = bm * 128 + wm + mi * 16 + lane / 4;
            int n = bn * 128 + wn + nf * 8 + 2 * (lane & 3);
            float2 b2 = *reinterpret_cast<const float2*>(&g_bias_r[n]);
            int t0 = m % TT, b0 = m / TT;
            int m8 = m + 8;
            int t1 = m8 % TT, b1 = m8 / TT;
            *reinterpret_cast<float2*>(&g_xg[((size_t)t0 * NB + b0) * GG + n]) =
                make_float2(acc[mi][nf][0] + b2.x, acc[mi][nf][1] + b2.y);
            *reinterpret_cast<float2*>(&g_xg[((size_t)t1 * NB + b1) * GG + n]) =
                make_float2(acc[mi][nf][2] + b2.x, acc[mi][nf][3] + b2.y);
        }
    }
}

// ---------------- fused LSTM step ----------------
// KG=2, BM=64, MF=2: 2 K-groups x 8 warps, warp tile 32x32, grid (32,4)=128 CTAs.
// stage=48KB, S=3 -> 144KB + 32KB xg = 176KB
#define STEP_BM      64
#define STEP_STAGE   (2 * STEP_BM * 128 + 2 * 128 * 128)
#define STEP_XG_OFF  (3 * STEP_STAGE)
#define STEP_SMEM    (STEP_XG_OFF + STEP_BM * 128 * 4)

__global__ __launch_bounds__(512, 1)
void lstm_step_mma(const bf16* __restrict__ h_hi, const bf16* __restrict__ h_lo,
                   bf16* __restrict__ hn_hi, bf16* __restrict__ hn_lo, int t) {
    extern __shared__ __align__(1024) char smem[];
    const uint32_t sbase = smem_u32(smem);
    const int bn = blockIdx.x, bm = blockIdx.y;
    const int tid = threadIdx.x, lane = tid & 31, wid = tid >> 5;

    // prefetch this tile's x-gates [64 rows x 128 cols f32] (joins cp group 0)
    {
        const float* xgsrc = g_xg + ((size_t)t * NB + bm * STEP_BM) * GG + bn * 128;
#pragma unroll
        for (int s = 0; s < 4; s++) {
            int i = tid + s * 512;
            int row = i >> 5, j = i & 31;
            cp16(sbase + STEP_XG_OFF + row * 512 + j * 16, xgsrc + (size_t)row * GG + j * 4);
        }
    }

    float acc[2][4][4];
#pragma unroll
    for (int i = 0; i < 2; i++)
#pragma unroll
        for (int j = 0; j < 4; j++)
#pragma unroll
            for (int k = 0; k < 4; k++) acc[i][j][k] = 0.0f;

    mma_mainloop<STEP_BM, 2, 2, 3>(h_hi, h_lo, g_Whh_hi, g_Whh_lo, HH,
                                   bm * STEP_BM, bn * 128, sbase, acc);

    // stage both K-groups' partial gates in smem: gsm[2][64][128]
    float* gsm = reinterpret_cast<float*>(smem);
    {
        const int kg = wid >> 3, w8 = wid & 7;
        const int wm = (w8 >> 2) * 32, wn = (w8 & 3) * 32;
#pragma unroll
        for (int mi = 0; mi < 2; mi++) {
#pragma unroll
            for (int nf = 0; nf < 4; nf++) {
                int r0 = wm + mi * 16 + lane / 4;
                int col = wn + nf * 8 + 2 * (lane & 3);
                *reinterpret_cast<float2*>(&gsm[kg * 8192 + r0 * 128 + col]) =
                    make_float2(acc[mi][nf][0], acc[mi][nf][1]);
                *reinterpret_cast<float2*>(&gsm[kg * 8192 + (r0 + 8) * 128 + col]) =
                    make_float2(acc[mi][nf][2], acc[mi][nf][3]);
            }
        }
    }
    __syncthreads();

    const float* xgsm = reinterpret_cast<const float*>(smem + STEP_XG_OFF);
#pragma unroll
    for (int it = 0; it < 4; it++) {
        int idx = it * 512 + tid;
        int m = idx >> 5, q = idx & 31;
        int mg = bm * STEP_BM + m;
        int qg = bn * 32 + q;
        float4 g0 = *reinterpret_cast<const float4*>(&gsm[m * 128 + q * 4]);
        float4 g1 = *reinterpret_cast<const float4*>(&gsm[8192 + m * 128 + q * 4]);
        float4 xv = *reinterpret_cast<const float4*>(&xgsm[m * 128 + q * 4]);
        float a0 = g0.x + g1.x + xv.x;
        float a1 = g0.y + g1.y + xv.y;
        float a2 = g0.z + g1.z + xv.z;
        float a3 = g0.w + g1.w + xv.w;
        float ig = 1.0f / (1.0f + expf(-a0));
        float fg = 1.0f / (1.0f + expf(-a1));
        float gg = tanhf(a2);
        float og = 1.0f / (1.0f + expf(-a3));
        float cn = fg * g_cbuf[mg * HH + qg] + ig * gg;
        g_cbuf[mg * HH + qg] = cn;
        float hv = og * tanhf(cn);
        g_hlast[mg * HH + qg] = hv;
        bf16 hi = __float2bfloat16(hv);
        hn_hi[(size_t)mg * HH + qg] = hi;
        hn_lo[(size_t)mg * HH + qg] = __float2bfloat16(hv - __bfloat162float(hi));
    }
}

// ---------------- fp32 SIMT GEMM (head only) ----------------
#define EPI_BIAS 0
#define EPI_RELU 1
template <int BM, int BN, int BK, int TM, int TN, int EPI>
__global__ void gemm_bias_kernel(const float* __restrict__ A,
                                 const float* __restrict__ B,
                                 const float* __restrict__ bias,
                                 float* __restrict__ C,
                                 int M, int N, int K) {
    constexpr int NT = (BM * BN) / (TM * TN);
    __shared__ float As[BK][BM];
    __shared__ float Bs[BK][BN];
    const int tid = threadIdx.x;
    const int bn = blockIdx.x, bm = blockIdx.y;
    const int tx = tid % (BN / TN);
    const int ty = tid / (BN / TN);
    const float* Ab = A + (size_t)bm * BM * K;
    const float* Bb = B + (size_t)bn * BN * K;
    float acc[TM][TN];
#pragma unroll
    for (int i = 0; i < TM; i++)
#pragma unroll
        for (int j = 0; j < TN; j++) acc[i][j] = 0.0f;
    for (int k0 = 0; k0 < K; k0 += BK) {
        constexpr int A4 = BM * BK / 4;
        constexpr int B4 = BN * BK / 4;
#pragma unroll
        for (int i0 = 0; i0 < A4; i0 += NT) {
            int i = i0 + tid;
            int r = i / (BK / 4), c = (i % (BK / 4)) * 4;
            float4 v = *reinterpret_cast<const float4*>(Ab + (size_t)r * K + k0 + c);
            As[c + 0][r] = v.x; As[c + 1][r] = v.y; As[c + 2][r] = v.z; As[c + 3][r] = v.w;
        }
#pragma unroll
        for (int i0 = 0; i0 < B4; i0 += NT) {
            int i = i0 + tid;
            int r = i / (BK / 4), c = (i % (BK / 4)) * 4;
            float4 v = *reinterpret_cast<const float4*>(Bb + (size_t)r * K + k0 + c);
            Bs[c + 0][r] = v.x; Bs[c + 1][r] = v.y; Bs[c + 2][r] = v.z; Bs[c + 3][r] = v.w;
        }
        __syncthreads();
#pragma unroll
        for (int k = 0; k < BK; k++) {
            float ra[TM], rb[TN];
#pragma unroll
            for (int i = 0; i < TM; i += 4) {
                float4 v = *reinterpret_cast<const float4*>(&As[k][ty * TM + i]);
                ra[i] = v.x; ra[i + 1] = v.y; ra[i + 2] = v.z; ra[i + 3] = v.w;
            }
#pragma unroll
            for (int j = 0; j < TN; j += 4) {
                float4 v = *reinterpret_cast<const float4*>(&Bs[k][tx * TN + j]);
                rb[j] = v.x; rb[j + 1] = v.y; rb[j + 2] = v.z; rb[j + 3] = v.w;
            }
#pragma unroll
            for (int i = 0; i < TM; i++)
#pragma unroll
                for (int j = 0; j < TN; j++) acc[i][j] += ra[i] * rb[j];
        }
        __syncthreads();
    }
#pragma unroll
    for (int i = 0; i < TM; i++) {
        int m = bm * BM + ty * TM + i;
#pragma unroll
        for (int j = 0; j < TN; j++) {
            int n = bn * BN + tx * TN + j;
            float v = acc[i][j] + bias[n];
            if (EPI == EPI_RELU) v = fmaxf(v, 0.0f);
            C[(size_t)m * N + n] = v;
        }
    }
}

// ---------------- host ----------------
extern "C" void kernel_launch(void* const* d_in, const int* in_sizes, int n_in,
                              void* d_out, int out_size) {
    const float* x    = (const float*)d_in[0];
    const float* W_ih = (const float*)d_in[1];
    const float* W_hh = (const float*)d_in[2];
    const float* b_ih = (const float*)d_in[3];
    const float* b_hh = (const float*)d_in[4];
    const float* W1   = (const float*)d_in[5];
    const float* b1   = (const float*)d_in[6];
    const float* W2   = (const float*)d_in[7];
    const float* b2   = (const float*)d_in[8];
    float* out = (float*)d_out;

    float* p_hlast;
    bf16 *p_hhi[2], *p_hlo[2];
    cudaGetSymbolAddress((void**)&p_hlast, g_hlast);
    {
        bf16* base;
        cudaGetSymbolAddress((void**)&base, g_h_hi);
        p_hhi[0] = base; p_hhi[1] = base + NB * HH;
        cudaGetSymbolAddress((void**)&base, g_h_lo);
        p_hlo[0] = base; p_hlo[1] = base + NB * HH;
    }

    static int attr_set = 0;
    if (!attr_set) {
        cudaFuncSetAttribute(lstm_step_mma, cudaFuncAttributeMaxDynamicSharedMemorySize, STEP_SMEM);
        cudaFuncSetAttribute(xgates_mma_kernel, cudaFuncAttributeMaxDynamicSharedMemorySize, XG_SMEM);
        attr_set = 1;
    }

    // 1) reorder + hi/lo split weights and x; zero state
    prep_kernel<<<1024, 256>>>(x, W_ih, W_hh, b_ih, b_hh);

    // 2) x_gates via HMMA, written transposed [t][batch][gate]
    xgates_mma_kernel<<<dim3(GG / 128, (NB * TT) / 128), 512, XG_SMEM>>>();

    // 3) 128 recurrent steps via HMMA, fused cell update
    for (int t = 0; t < TT; t++) {
        int a = t & 1, b = (t + 1) & 1;
        lstm_step_mma<<<dim3(GG / 128, NB / STEP_BM), 512, STEP_SMEM>>>(
            p_hhi[a], p_hlo[a], p_hhi[b], p_hlo[b], t);
    }

    // 4) head (fp32 SIMT)
    float* pre_out = out + NB * OUTD;
    gemm_bias_kernel<64, 128, 16, 4, 8, EPI_RELU>
        <<<dim3(HH / 128, NB / 64), 256>>>(p_hlast, W1, b1, pre_out, NB, HH, HH);
    gemm_bias_kernel<64, 128, 16, 4, 8, EPI_BIAS>
        <<<dim3(OUTD / 128, NB / 64), 256>>>(pre_out, W2, b2, out, NB, OUTD, HH);
}

// round 11
// speedup vs baseline: 1.0770x; 1.0770x over previous
#include <cuda_runtime.h>
#include <cuda_bf16.h>
#include <math.h>
#include <stdint.h>

// Problem dims (fixed)
#define NB   256
#define TT   128
#define DD   512
#define HH   1024
#define GG   4096
#define OUTD 128

typedef __nv_bfloat16 bf16;

// ---------------- device scratch (pre-swizzled tile blocks) ----------------
// ALL bulk-copy sources MUST be >=16B aligned; use 1024 for safety.
//  W_hh: [bn(32)][kc(16)] 32KB blocks: [hi 16KB (128 rows x 128B) | lo 16KB]
//  W_ih: [bn(32)][kc(8)]  32KB blocks: same
//  x:    [bm(256)][kc(8)] 32KB blocks: [hi 16KB (128 rows) | lo 16KB]
//  h:    [buf(2)][bm(4)][kc(16)] 16KB blocks: [hi 8KB (64 rows) | lo 8KB]
//  xg:   [t(128)][bm(4)][bn(32)] 32KB blocks: 64 rows x 128 cols f32 (no swizzle)
__device__ __align__(1024) char g_WhhT[(size_t)32 * 16 * 32768];
__device__ __align__(1024) char g_WihT[(size_t)32 * 8 * 32768];
__device__ __align__(1024) char g_xT[(size_t)256 * 8 * 32768];
__device__ __align__(1024) char g_hT[2][(size_t)4 * 16 * 16384];
__device__ __align__(1024) float g_xg[(size_t)TT * 4 * 32 * 8192];
__device__ float g_bias_r[GG];
__device__ float g_hlast[NB * HH];
__device__ float g_cbuf[NB * HH];

// ---------------- low-level helpers ----------------
__device__ __forceinline__ uint32_t smem_u32(const void* p) {
    uint32_t a;
    asm("{ .reg .u64 t; cvta.to.shared.u64 t, %1; cvt.u32.u64 %0, t; }" : "=r"(a) : "l"(p));
    return a;
}
__device__ __forceinline__ void ldsm4(uint32_t* r, uint32_t addr) {
    asm volatile("ldmatrix.sync.aligned.m8n8.x4.shared.b16 {%0,%1,%2,%3}, [%4];"
                 : "=r"(r[0]), "=r"(r[1]), "=r"(r[2]), "=r"(r[3]) : "r"(addr));
}
__device__ __forceinline__ void mma16816(float* d, const uint32_t* a, uint32_t b0, uint32_t b1) {
    asm volatile(
        "mma.sync.aligned.m16n8k16.row.col.f32.bf16.bf16.f32 "
        "{%0,%1,%2,%3}, {%4,%5,%6,%7}, {%8,%9}, {%0,%1,%2,%3};"
        : "+f"(d[0]), "+f"(d[1]), "+f"(d[2]), "+f"(d[3])
        : "r"(a[0]), "r"(a[1]), "r"(a[2]), "r"(a[3]), "r"(b0), "r"(b1));
}
__device__ __forceinline__ void bulk_g2s(uint32_t dst, const void* src, uint32_t bytes, uint32_t mb) {
    asm volatile("cp.async.bulk.shared::cta.global.mbarrier::complete_tx::bytes [%0], [%1], %2, [%3];"
                 :: "r"(dst), "l"(__cvta_generic_to_global(src)), "r"(bytes), "r"(mb) : "memory");
}
#define MBAR_INIT(mb, cnt) \
    asm volatile("mbarrier.init.shared.b64 [%0], %1;" :: "r"(mb), "r"(cnt) : "memory")
#define MBAR_EXPECT_TX(mb, bytes) \
    asm volatile("mbarrier.arrive.expect_tx.shared.b64 _, [%0], %1;" :: "r"(mb), "r"(bytes) : "memory")
// try_wait with suspend-time hint: HW-sleep poll loop (documented pattern)
#define MBAR_WAIT(mb, ph) do { \
    asm volatile("{\n\t.reg .pred P;\n\tW_%=:\n\t" \
                 "mbarrier.try_wait.parity.shared::cta.b64 P, [%0], %1, 0x989680;\n\t" \
                 "@P bra.uni D_%=;\n\tbra.uni W_%=;\n\tD_%=:\n\t}" \
                 :: "r"(mb), "r"(ph) : "memory"); } while (0)

// within a 128B row: 16B chunk j stored at j ^ (row & 7)
__device__ __forceinline__ uint32_t swz(int row, int j) {
    return (uint32_t)(row * 128 + ((j ^ (row & 7)) << 4));
}
// swizzled byte offset inside a [rows x 64 bf16] half-block
__device__ __forceinline__ uint32_t tile_off(int row, int col) {
    return (uint32_t)(row * 128 + (((col >> 3) ^ (row & 7)) << 4) + (col & 7) * 2);
}

// ---------------- prep: build pre-swizzled tiles ----------------
__global__ void prep_kernel(const float* __restrict__ x,
                            const float* __restrict__ Wih,
                            const float* __restrict__ Whh,
                            const float* __restrict__ bih,
                            const float* __restrict__ bhh) {
    int idx = blockIdx.x * blockDim.x + threadIdx.x;
    int stride = gridDim.x * blockDim.x;
    // W_ih: gate-interleaved row rn=4q+p <-> old row p*HH+q
    for (int i = idx; i < GG * DD; i += stride) {
        int rn = i / DD, d = i - rn * DD;
        int q = rn >> 2, p = rn & 3;
        float w = Wih[(p * HH + q) * DD + d];
        bf16 hi = __float2bfloat16(w);
        bf16 lo = __float2bfloat16(w - __bfloat162float(hi));
        char* base = g_WihT + (((size_t)(rn >> 7) * 8 + (d >> 6)) * 32768);
        uint32_t so = tile_off(rn & 127, d & 63);
        *(bf16*)(base + so) = hi;
        *(bf16*)(base + 16384 + so) = lo;
    }
    // W_hh
    for (int i = idx; i < GG * HH; i += stride) {
        int rn = i / HH, d = i - rn * HH;
        int q = rn >> 2, p = rn & 3;
        float w = Whh[(p * HH + q) * HH + d];
        bf16 hi = __float2bfloat16(w);
        bf16 lo = __float2bfloat16(w - __bfloat162float(hi));
        char* base = g_WhhT + (((size_t)(rn >> 7) * 16 + (d >> 6)) * 32768);
        uint32_t so = tile_off(rn & 127, d & 63);
        *(bf16*)(base + so) = hi;
        *(bf16*)(base + 16384 + so) = lo;
    }
    // x tiles
    for (size_t i = idx; i < (size_t)NB * TT * DD; i += stride) {
        int m = (int)(i / DD), d = (int)(i - (size_t)m * DD);
        float v = x[i];
        bf16 hi = __float2bfloat16(v);
        bf16 lo = __float2bfloat16(v - __bfloat162float(hi));
        char* base = g_xT + (((size_t)(m >> 7) * 8 + (d >> 6)) * 32768);
        uint32_t so = tile_off(m & 127, d & 63);
        *(bf16*)(base + so) = hi;
        *(bf16*)(base + 16384 + so) = lo;
    }
    for (int i = idx; i < GG; i += stride) {
        int q = i >> 2, p = i & 3;
        g_bias_r[i] = bih[p * HH + q] + bhh[p * HH + q];
    }
    // zero h buf0 tiles + c
    for (int i = idx; i < 4 * 16 * 16384 / 4; i += stride)
        reinterpret_cast<uint32_t*>(g_hT[0])[i] = 0;
    for (int i = idx; i < NB * HH; i += stride)
        g_cbuf[i] = 0.0f;
}

// ---------------- bulk-async multistage HMMA mainloop (512 threads) ----------------
// Per K-chunk: ONE expect_tx + 2 bulk copies (A block, B block). 3 MMA passes
// (hi*hi, hi*lo, lo*hi) reuse register fragments.
// KG=1: 16 warps 4(M)x4(N); KG=2: 2 K-groups x 8 warps (2Mx4N), separate accs.
template <int MF, int KG, int ABYTES>
__device__ __forceinline__ void mma_mainloop_tma(
    const char* __restrict__ Ablk, const char* __restrict__ Bblk, int KC,
    uint32_t sbase, uint32_t mbase, float acc[MF][4][4]) {
    constexpr int S = 3;
    constexpr int STAGE = ABYTES + 32768;
    constexpr int KSUB = 4 / KG;
    const int tid = threadIdx.x;
    const int lane = tid & 31, wid = tid >> 5;
    const int kg = (KG == 2) ? (wid >> 3) : 0;
    const int w8 = (KG == 2) ? (wid & 7) : wid;
    const int wm = (w8 >> 2) * (16 * MF);
    const int wn = (w8 & 3) * 32;

    auto issue = [&](int ci) {
        uint32_t mb = mbase + 8u * (ci % S);
        uint32_t dst = sbase + (uint32_t)(ci % S) * STAGE;
        MBAR_EXPECT_TX(mb, (uint32_t)(ABYTES + 32768));
        bulk_g2s(dst, Ablk + (size_t)ci * ABYTES, ABYTES, mb);
        bulk_g2s(dst + ABYTES, Bblk + (size_t)ci * 32768, 32768, mb);
    };

    if (tid == 0) { issue(0); if (KC > 1) issue(1); }

    for (int ci = 0; ci < KC; ci++) {
        MBAR_WAIT(mbase + 8u * (ci % S), (uint32_t)((ci / S) & 1));
        __syncthreads();
        if (tid == 0 && ci + 2 < KC) issue(ci + 2);
        uint32_t st = sbase + (uint32_t)(ci % S) * STAGE;
        uint32_t sAh = st, sAl = st + ABYTES / 2;
        uint32_t sBh = st + ABYTES, sBl = st + ABYTES + 16384;
#pragma unroll
        for (int ks2 = 0; ks2 < KSUB; ks2++) {
            const int ks = kg * KSUB + ks2;
            uint32_t ah[MF][4], al[MF][4], bh[2][4], bl[2][4];
            const int j = ks * 2 + (lane >> 4);
#pragma unroll
            for (int mi = 0; mi < MF; mi++) {
                int row = wm + mi * 16 + (lane & 15);
                uint32_t so = swz(row, j);
                ldsm4(ah[mi], sAh + so);
                ldsm4(al[mi], sAl + so);
            }
#pragma unroll
            for (int bi = 0; bi < 2; bi++) {
                int row = wn + bi * 16 + (lane & 15);
                uint32_t so = swz(row, j);
                ldsm4(bh[bi], sBh + so);
                ldsm4(bl[bi], sBl + so);
            }
#pragma unroll
            for (int mi = 0; mi < MF; mi++)
#pragma unroll
                for (int nf = 0; nf < 4; nf++)
                    mma16816(acc[mi][nf], ah[mi], bh[nf >> 1][nf & 1], bh[nf >> 1][(nf & 1) + 2]);
#pragma unroll
            for (int mi = 0; mi < MF; mi++)
#pragma unroll
                for (int nf = 0; nf < 4; nf++)
                    mma16816(acc[mi][nf], ah[mi], bl[nf >> 1][nf & 1], bl[nf >> 1][(nf & 1) + 2]);
#pragma unroll
            for (int mi = 0; mi < MF; mi++)
#pragma unroll
                for (int nf = 0; nf < 4; nf++)
                    mma16816(acc[mi][nf], al[mi], bh[nf >> 1][nf & 1], bh[nf >> 1][(nf & 1) + 2]);
        }
    }
    __syncthreads();
}

// ---------------- xgates: A = x tiles, B = Wih tiles; writes tiled g_xg ----------------
// KG=1, MF=2, ABYTES=32768, KC=8; smem = 3*64KB + 64
#define XG_SMEM (3 * (32768 + 32768) + 64)

__global__ __launch_bounds__(512, 1)
void xgates_mma_kernel() {
    extern __shared__ __align__(1024) char smem[];
    const uint32_t sbase = smem_u32(smem);
    const uint32_t mbase = sbase + 3 * (32768 + 32768);
    const int bn = blockIdx.x, bm = blockIdx.y;
    const int tid = threadIdx.x, lane = tid & 31, wid = tid >> 5;
    const int wm = (wid >> 2) * 32, wn = (wid & 3) * 32;

    if (tid == 0) { MBAR_INIT(mbase, 1); MBAR_INIT(mbase + 8, 1); MBAR_INIT(mbase + 16, 1); }
    __syncthreads();

    float acc[2][4][4];
#pragma unroll
    for (int i = 0; i < 2; i++)
#pragma unroll
        for (int j = 0; j < 4; j++)
#pragma unroll
            for (int k = 0; k < 4; k++) acc[i][j][k] = 0.0f;

    mma_mainloop_tma<2, 1, 32768>(
        g_xT + (size_t)bm * 8 * 32768, g_WihT + (size_t)bn * 8 * 32768, 8,
        sbase, mbase, acc);

#pragma unroll
    for (int mi = 0; mi < 2; mi++) {
#pragma unroll
        for (int nf = 0; nf < 4; nf++) {
            int m = bm * 128 + wm + mi * 16 + lane / 4;   // token
            int n = bn * 128 + wn + nf * 8 + 2 * (lane & 3);
            float2 b2 = *reinterpret_cast<const float2*>(&g_bias_r[n]);
            // token m = b*TT + t  ->  xg tile [t][b>>6][n>>7], row b&63, col n&127
            int t0 = m % TT, b0 = m / TT;
            int m8 = m + 8;
            int t1 = m8 % TT, b1 = m8 / TT;
            size_t o0 = ((((size_t)t0 * 4 + (b0 >> 6)) * 32 + (n >> 7)) * 8192) + (b0 & 63) * 128 + (n & 127);
            size_t o1 = ((((size_t)t1 * 4 + (b1 >> 6)) * 32 + (n >> 7)) * 8192) + (b1 & 63) * 128 + (n & 127);
            *reinterpret_cast<float2*>(&g_xg[o0]) =
                make_float2(acc[mi][nf][0] + b2.x, acc[mi][nf][1] + b2.y);
            *reinterpret_cast<float2*>(&g_xg[o1]) =
                make_float2(acc[mi][nf][2] + b2.x, acc[mi][nf][3] + b2.y);
        }
    }
}

// ---------------- fused LSTM step ----------------
// KG=2, MF=2, ABYTES=16384, KC=16; grid (32,4)=128 CTAs, 512 threads.
// smem: 3*48KB stages + 32KB xg + 64 mbar
#define STEP_STAGE   (16384 + 32768)
#define STEP_XG_OFF  (3 * STEP_STAGE)
#define STEP_MB_OFF  (STEP_XG_OFF + 32768)
#define STEP_SMEM    (STEP_MB_OFF + 64)

__global__ __launch_bounds__(512, 1)
void lstm_step_mma(int t, int buf) {
    extern __shared__ __align__(1024) char smem[];
    const uint32_t sbase = smem_u32(smem);
    const uint32_t mbase = sbase + STEP_MB_OFF;
    const int bn = blockIdx.x, bm = blockIdx.y;
    const int tid = threadIdx.x, lane = tid & 31, wid = tid >> 5;

    if (tid == 0) {
        MBAR_INIT(mbase, 1); MBAR_INIT(mbase + 8, 1);
        MBAR_INIT(mbase + 16, 1); MBAR_INIT(mbase + 24, 1);
    }
    __syncthreads();
    // xg tile bulk (own barrier, used once this launch -> parity 0)
    if (tid == 0) {
        MBAR_EXPECT_TX(mbase + 24, 32768u);
        bulk_g2s(sbase + STEP_XG_OFF,
                 (const char*)g_xg + (((size_t)t * 4 + bm) * 32 + bn) * 32768,
                 32768u, mbase + 24);
    }

    float acc[2][4][4];
#pragma unroll
    for (int i = 0; i < 2; i++)
#pragma unroll
        for (int j = 0; j < 4; j++)
#pragma unroll
            for (int k = 0; k < 4; k++) acc[i][j][k] = 0.0f;

    mma_mainloop_tma<2, 2, 16384>(
        g_hT[buf] + (size_t)bm * 16 * 16384, g_WhhT + (size_t)bn * 16 * 32768, 16,
        sbase, mbase, acc);

    // stage both K-groups' partial gates in smem: gsm[2][64][128] (stage area free)
    float* gsm = reinterpret_cast<float*>(smem);
    {
        const int kg = wid >> 3, w8 = wid & 7;
        const int wm = (w8 >> 2) * 32, wn = (w8 & 3) * 32;
#pragma unroll
        for (int mi = 0; mi < 2; mi++) {
#pragma unroll
            for (int nf = 0; nf < 4; nf++) {
                int r0 = wm + mi * 16 + lane / 4;
                int col = wn + nf * 8 + 2 * (lane & 3);
                *reinterpret_cast<float2*>(&gsm[kg * 8192 + r0 * 128 + col]) =
                    make_float2(acc[mi][nf][0], acc[mi][nf][1]);
                *reinterpret_cast<float2*>(&gsm[kg * 8192 + (r0 + 8) * 128 + col]) =
                    make_float2(acc[mi][nf][2], acc[mi][nf][3]);
            }
        }
    }
    MBAR_WAIT(mbase + 24, 0u);
    __syncthreads();

    const float* xgsm = reinterpret_cast<const float*>(smem + STEP_XG_OFF);
    char* hout = g_hT[buf ^ 1];
#pragma unroll
    for (int it = 0; it < 4; it++) {
        int idx = it * 512 + tid;
        int m = idx >> 5, q = idx & 31;
        int mg = bm * 64 + m;
        int qg = bn * 32 + q;
        float4 g0 = *reinterpret_cast<const float4*>(&gsm[m * 128 + q * 4]);
        float4 g1 = *reinterpret_cast<const float4*>(&gsm[8192 + m * 128 + q * 4]);
        float4 xv = *reinterpret_cast<const float4*>(&xgsm[m * 128 + q * 4]);
        float a0 = g0.x + g1.x + xv.x;
        float a1 = g0.y + g1.y + xv.y;
        float a2 = g0.z + g1.z + xv.z;
        float a3 = g0.w + g1.w + xv.w;
        float ig = 1.0f / (1.0f + expf(-a0));
        float fg = 1.0f / (1.0f + expf(-a1));
        float gg = tanhf(a2);
        float og = 1.0f / (1.0f + expf(-a3));
        float cn = fg * g_cbuf[mg * HH + qg] + ig * gg;
        g_cbuf[mg * HH + qg] = cn;
        float hv = og * tanhf(cn);
        g_hlast[mg * HH + qg] = hv;
        bf16 hib = __float2bfloat16(hv);
        bf16 lob = __float2bfloat16(hv - __bfloat162float(hib));
        // write next h in tiled-swizzled form: tile (bm, qg>>6), row m, col qg&63
        char* base = hout + ((size_t)(bm * 16 + (qg >> 6))) * 16384;
        uint32_t so = tile_off(m, qg & 63);
        *(bf16*)(base + so) = hib;
        *(bf16*)(base + 8192 + so) = lob;
    }
}

// ---------------- fp32 SIMT GEMM (head only) ----------------
#define EPI_BIAS 0
#define EPI_RELU 1
template <int BM, int BN, int BK, int TM, int TN, int EPI>
__global__ void gemm_bias_kernel(const float* __restrict__ A,
                                 const float* __restrict__ B,
                                 const float* __restrict__ bias,
                                 float* __restrict__ C,
                                 int M, int N, int K) {
    constexpr int NT = (BM * BN) / (TM * TN);
    __shared__ float As[BK][BM];
    __shared__ float Bs[BK][BN];
    const int tid = threadIdx.x;
    const int bn = blockIdx.x, bm = blockIdx.y;
    const int tx = tid % (BN / TN);
    const int ty = tid / (BN / TN);
    const float* Ab = A + (size_t)bm * BM * K;
    const float* Bb = B + (size_t)bn * BN * K;
    float acc[TM][TN];
#pragma unroll
    for (int i = 0; i < TM; i++)
#pragma unroll
        for (int j = 0; j < TN; j++) acc[i][j] = 0.0f;
    for (int k0 = 0; k0 < K; k0 += BK) {
        constexpr int A4 = BM * BK / 4;
        constexpr int B4 = BN * BK / 4;
#pragma unroll
        for (int i0 = 0; i0 < A4; i0 += NT) {
            int i = i0 + tid;
            int r = i / (BK / 4), c = (i % (BK / 4)) * 4;
            float4 v = *reinterpret_cast<const float4*>(Ab + (size_t)r * K + k0 + c);
            As[c + 0][r] = v.x; As[c + 1][r] = v.y; As[c + 2][r] = v.z; As[c + 3][r] = v.w;
        }
#pragma unroll
        for (int i0 = 0; i0 < B4; i0 += NT) {
            int i = i0 + tid;
            int r = i / (BK / 4), c = (i % (BK / 4)) * 4;
            float4 v = *reinterpret_cast<const float4*>(Bb + (size_t)r * K + k0 + c);
            Bs[c + 0][r] = v.x; Bs[c + 1][r] = v.y; Bs[c + 2][r] = v.z; Bs[c + 3][r] = v.w;
        }
        __syncthreads();
#pragma unroll
        for (int k = 0; k < BK; k++) {
            float ra[TM], rb[TN];
#pragma unroll
            for (int i = 0; i < TM; i += 4) {
                float4 v = *reinterpret_cast<const float4*>(&As[k][ty * TM + i]);
                ra[i] = v.x; ra[i + 1] = v.y; ra[i + 2] = v.z; ra[i + 3] = v.w;
            }
#pragma unroll
            for (int j = 0; j < TN; j += 4) {
                float4 v = *reinterpret_cast<const float4*>(&Bs[k][tx * TN + j]);
                rb[j] = v.x; rb[j + 1] = v.y; rb[j + 2] = v.z; rb[j + 3] = v.w;
            }
#pragma unroll
            for (int i = 0; i < TM; i++)
#pragma unroll
                for (int j = 0; j < TN; j++) acc[i][j] += ra[i] * rb[j];
        }
        __syncthreads();
    }
#pragma unroll
    for (int i = 0; i < TM; i++) {
        int m = bm * BM + ty * TM + i;
#pragma unroll
        for (int j = 0; j < TN; j++) {
            int n = bn * BN + tx * TN + j;
            float v = acc[i][j] + bias[n];
            if (EPI == EPI_RELU) v = fmaxf(v, 0.0f);
            C[(size_t)m * N + n] = v;
        }
    }
}

// ---------------- host ----------------
extern "C" void kernel_launch(void* const* d_in, const int* in_sizes, int n_in,
                              void* d_out, int out_size) {
    const float* x    = (const float*)d_in[0];
    const float* W_ih = (const float*)d_in[1];
    const float* W_hh = (const float*)d_in[2];
    const float* b_ih = (const float*)d_in[3];
    const float* b_hh = (const float*)d_in[4];
    const float* W1   = (const float*)d_in[5];
    const float* b1   = (const float*)d_in[6];
    const float* W2   = (const float*)d_in[7];
    const float* b2   = (const float*)d_in[8];
    float* out = (float*)d_out;

    float* p_hlast;
    cudaGetSymbolAddress((void**)&p_hlast, g_hlast);

    static int attr_set = 0;
    if (!attr_set) {
        cudaFuncSetAttribute(lstm_step_mma, cudaFuncAttributeMaxDynamicSharedMemorySize, STEP_SMEM);
        cudaFuncSetAttribute(xgates_mma_kernel, cudaFuncAttributeMaxDynamicSharedMemorySize, XG_SMEM);
        attr_set = 1;
    }

    // 1) pre-swizzled tiles for W_ih / W_hh / x; bias; zero state
    prep_kernel<<<1024, 256>>>(x, W_ih, W_hh, b_ih, b_hh);

    // 2) x_gates via HMMA + bulk-async, written in xg tile blocks
    xgates_mma_kernel<<<dim3(GG / 128, (NB * TT) / 128), 512, XG_SMEM>>>();

    // 3) 128 recurrent steps
    for (int t = 0; t < TT; t++)
        lstm_step_mma<<<dim3(GG / 128, NB / 64), 512, STEP_SMEM>>>(t, t & 1);

    // 4) head (fp32 SIMT)
    float* pre_out = out + NB * OUTD;
    gemm_bias_kernel<64, 128, 16, 4, 8, EPI_RELU>
        <<<dim3(HH / 128, NB / 64), 256>>>(p_hlast, W1, b1, pre_out, NB, HH, HH);
    gemm_bias_kernel<64, 128, 16, 4, 8, EPI_BIAS>
        <<<dim3(OUTD / 128, NB / 64), 256>>>(pre_out, W2, b2, out, NB, OUTD, HH);
}

// round 13
// speedup vs baseline: 1.1239x; 1.0435x over previous
#include <cuda_runtime.h>
#include <cuda_bf16.h>
#include <math.h>
#include <stdint.h>

// Problem dims (fixed)
#define NB   256
#define TT   128
#define DD   512
#define HH   1024
#define GG   4096
#define OUTD 128

typedef __nv_bfloat16 bf16;

// ---------------- device scratch (pre-swizzled tile blocks) ----------------
// ALL bulk-copy sources MUST be >=16B aligned; use 1024 for safety.
__device__ __align__(1024) char g_WhhT[(size_t)32 * 16 * 32768];
__device__ __align__(1024) char g_WihT[(size_t)32 * 8 * 32768];
__device__ __align__(1024) char g_xT[(size_t)256 * 8 * 32768];
__device__ __align__(1024) char g_hT[2][(size_t)4 * 16 * 16384];
__device__ __align__(1024) float g_xg[(size_t)TT * 4 * 32 * 8192];
__device__ float g_bias_r[GG];
__device__ float g_hlast[NB * HH];
__device__ float g_cbuf[NB * HH];

// ---------------- low-level helpers ----------------
__device__ __forceinline__ uint32_t smem_u32(const void* p) {
    uint32_t a;
    asm("{ .reg .u64 t; cvta.to.shared.u64 t, %1; cvt.u32.u64 %0, t; }" : "=r"(a) : "l"(p));
    return a;
}
__device__ __forceinline__ void ldsm4(uint32_t* r, uint32_t addr) {
    asm volatile("ldmatrix.sync.aligned.m8n8.x4.shared.b16 {%0,%1,%2,%3}, [%4];"
                 : "=r"(r[0]), "=r"(r[1]), "=r"(r[2]), "=r"(r[3]) : "r"(addr));
}
__device__ __forceinline__ void mma16816(float* d, const uint32_t* a, uint32_t b0, uint32_t b1) {
    asm volatile(
        "mma.sync.aligned.m16n8k16.row.col.f32.bf16.bf16.f32 "
        "{%0,%1,%2,%3}, {%4,%5,%6,%7}, {%8,%9}, {%0,%1,%2,%3};"
        : "+f"(d[0]), "+f"(d[1]), "+f"(d[2]), "+f"(d[3])
        : "r"(a[0]), "r"(a[1]), "r"(a[2]), "r"(a[3]), "r"(b0), "r"(b1));
}
__device__ __forceinline__ void bulk_g2s(uint32_t dst, const void* src, uint32_t bytes, uint32_t mb) {
    asm volatile("cp.async.bulk.shared::cta.global.mbarrier::complete_tx::bytes [%0], [%1], %2, [%3];"
                 :: "r"(dst), "l"(__cvta_generic_to_global(src)), "r"(bytes), "r"(mb) : "memory");
}
#define MBAR_INIT(mb, cnt) \
    asm volatile("mbarrier.init.shared.b64 [%0], %1;" :: "r"(mb), "r"(cnt) : "memory")
#define MBAR_EXPECT_TX(mb, bytes) \
    asm volatile("mbarrier.arrive.expect_tx.shared.b64 _, [%0], %1;" :: "r"(mb), "r"(bytes) : "memory")
#define MBAR_ARRIVE(mb) \
    asm volatile("mbarrier.arrive.shared.b64 _, [%0];" :: "r"(mb) : "memory")
#define MBAR_WAIT(mb, ph) do { \
    asm volatile("{\n\t.reg .pred P;\n\tW_%=:\n\t" \
                 "mbarrier.try_wait.parity.acquire.cta.shared::cta.b64 P, [%0], %1, 0x989680;\n\t" \
                 "@P bra.uni D_%=;\n\tbra.uni W_%=;\n\tD_%=:\n\t}" \
                 :: "r"(mb), "r"(ph) : "memory"); } while (0)

// within a 128B row: 16B chunk j stored at j ^ (row & 7)
__device__ __forceinline__ uint32_t swz(int row, int j) {
    return (uint32_t)(row * 128 + ((j ^ (row & 7)) << 4));
}
// swizzled byte offset inside a [rows x 64 bf16] half-block
__device__ __forceinline__ uint32_t tile_off(int row, int col) {
    return (uint32_t)(row * 128 + (((col >> 3) ^ (row & 7)) << 4) + (col & 7) * 2);
}

// ---------------- prep: build pre-swizzled tiles ----------------
__global__ void prep_kernel(const float* __restrict__ x,
                            const float* __restrict__ Wih,
                            const float* __restrict__ Whh,
                            const float* __restrict__ bih,
                            const float* __restrict__ bhh) {
    int idx = blockIdx.x * blockDim.x + threadIdx.x;
    int stride = gridDim.x * blockDim.x;
    for (int i = idx; i < GG * DD; i += stride) {
        int rn = i / DD, d = i - rn * DD;
        int q = rn >> 2, p = rn & 3;
        float w = Wih[(p * HH + q) * DD + d];
        bf16 hi = __float2bfloat16(w);
        bf16 lo = __float2bfloat16(w - __bfloat162float(hi));
        char* base = g_WihT + (((size_t)(rn >> 7) * 8 + (d >> 6)) * 32768);
        uint32_t so = tile_off(rn & 127, d & 63);
        *(bf16*)(base + so) = hi;
        *(bf16*)(base + 16384 + so) = lo;
    }
    for (int i = idx; i < GG * HH; i += stride) {
        int rn = i / HH, d = i - rn * HH;
        int q = rn >> 2, p = rn & 3;
        float w = Whh[(p * HH + q) * HH + d];
        bf16 hi = __float2bfloat16(w);
        bf16 lo = __float2bfloat16(w - __bfloat162float(hi));
        char* base = g_WhhT + (((size_t)(rn >> 7) * 16 + (d >> 6)) * 32768);
        uint32_t so = tile_off(rn & 127, d & 63);
        *(bf16*)(base + so) = hi;
        *(bf16*)(base + 16384 + so) = lo;
    }
    for (size_t i = idx; i < (size_t)NB * TT * DD; i += stride) {
        int m = (int)(i / DD), d = (int)(i - (size_t)m * DD);
        float v = x[i];
        bf16 hi = __float2bfloat16(v);
        bf16 lo = __float2bfloat16(v - __bfloat162float(hi));
        char* base = g_xT + (((size_t)(m >> 7) * 8 + (d >> 6)) * 32768);
        uint32_t so = tile_off(m & 127, d & 63);
        *(bf16*)(base + so) = hi;
        *(bf16*)(base + 16384 + so) = lo;
    }
    for (int i = idx; i < GG; i += stride) {
        int q = i >> 2, p = i & 3;
        g_bias_r[i] = bih[p * HH + q] + bhh[p * HH + q];
    }
    for (int i = idx; i < 4 * 16 * 16384 / 4; i += stride)
        reinterpret_cast<uint32_t*>(g_hT[0])[i] = 0;
    for (int i = idx; i < NB * HH; i += stride)
        g_cbuf[i] = 0.0f;
}

// ---------------- producer/consumer bulk-async HMMA mainloop (512 thr) ----------------
// full[s] = tx barrier (DMA completion); empty[s] = 16 arrivals (1/warp).
// No per-chunk __syncthreads: warps run decoupled, up to S-1 chunks of slack.
// Barrier layout at mbase: full[s] = +8*s, empty[s] = +8*(S+s).
template <int MF, int KG, int ABYTES, int S>
__device__ __forceinline__ void mma_mainloop_tma(
    const char* __restrict__ Ablk, const char* __restrict__ Bblk, int KC,
    uint32_t sbase, uint32_t mbase, float acc[MF][4][4]) {
    constexpr int STAGE = ABYTES + 32768;
    constexpr int KSUB = 4 / KG;
    const int tid = threadIdx.x;
    const int lane = tid & 31, wid = tid >> 5;
    const int kg = (KG == 2) ? (wid >> 3) : 0;
    const int w8 = (KG == 2) ? (wid & 7) : wid;
    const int wm = (w8 >> 2) * (16 * MF);
    const int wn = (w8 & 3) * 32;
    const bool prod = (tid == 0);

    auto issue = [&](int ci) {
        int s = ci % S;
        uint32_t mb = mbase + 8u * s;
        uint32_t dst = sbase + (uint32_t)s * STAGE;
        MBAR_EXPECT_TX(mb, (uint32_t)(ABYTES + 32768));
        bulk_g2s(dst, Ablk + (size_t)ci * ABYTES, ABYTES, mb);
        bulk_g2s(dst + ABYTES, Bblk + (size_t)ci * 32768, 32768, mb);
    };

    if (prod) {
#pragma unroll
        for (int s = 0; s < S; s++)
            if (s < KC) issue(s);
    }

    for (int ci = 0; ci < KC; ci++) {
        const int s = ci % S;
        const uint32_t ph = (uint32_t)((ci / S) & 1);
        MBAR_WAIT(mbase + 8u * s, ph);              // full[s]
        uint32_t st = sbase + (uint32_t)s * STAGE;
        uint32_t sAh = st, sAl = st + ABYTES / 2;
        uint32_t sBh = st + ABYTES, sBl = st + ABYTES + 16384;
#pragma unroll
        for (int ks2 = 0; ks2 < KSUB; ks2++) {
            const int ks = kg * KSUB + ks2;
            uint32_t ah[MF][4], al[MF][4], bh[2][4], bl[2][4];
            const int j = ks * 2 + (lane >> 4);
#pragma unroll
            for (int mi = 0; mi < MF; mi++) {
                int row = wm + mi * 16 + (lane & 15);
                uint32_t so = swz(row, j);
                ldsm4(ah[mi], sAh + so);
                ldsm4(al[mi], sAl + so);
            }
#pragma unroll
            for (int bi = 0; bi < 2; bi++) {
                int row = wn + bi * 16 + (lane & 15);
                uint32_t so = swz(row, j);
                ldsm4(bh[bi], sBh + so);
                ldsm4(bl[bi], sBl + so);
            }
#pragma unroll
            for (int mi = 0; mi < MF; mi++)
#pragma unroll
                for (int nf = 0; nf < 4; nf++)
                    mma16816(acc[mi][nf], ah[mi], bh[nf >> 1][nf & 1], bh[nf >> 1][(nf & 1) + 2]);
#pragma unroll
            for (int mi = 0; mi < MF; mi++)
#pragma unroll
                for (int nf = 0; nf < 4; nf++)
                    mma16816(acc[mi][nf], ah[mi], bl[nf >> 1][nf & 1], bl[nf >> 1][(nf & 1) + 2]);
#pragma unroll
            for (int mi = 0; mi < MF; mi++)
#pragma unroll
                for (int nf = 0; nf < 4; nf++)
                    mma16816(acc[mi][nf], al[mi], bh[nf >> 1][nf & 1], bh[nf >> 1][(nf & 1) + 2]);
        }
        if (lane == 0) MBAR_ARRIVE(mbase + 8u * (S + s));   // empty[s]
        if (prod && ci + S < KC) {
            MBAR_WAIT(mbase + 8u * (S + s), ph);            // consumers done with s
            issue(ci + S);
        }
    }
    __syncthreads();   // protect stage buffers before epilogue reuse
}

// ---------------- xgates: A = x tiles, B = Wih tiles; writes tiled g_xg ----------------
// KG=1, MF=2, ABYTES=32768, KC=8, S=3; smem = 3*64KB + 128
#define XG_MB_OFF (3 * (32768 + 32768))
#define XG_SMEM   (XG_MB_OFF + 128)

__global__ __launch_bounds__(512, 1)
void xgates_mma_kernel() {
    extern __shared__ __align__(1024) char smem[];
    const uint32_t sbase = smem_u32(smem);
    const uint32_t mbase = sbase + XG_MB_OFF;
    const int bn = blockIdx.x, bm = blockIdx.y;
    const int tid = threadIdx.x, lane = tid & 31, wid = tid >> 5;
    const int wm = (wid >> 2) * 32, wn = (wid & 3) * 32;

    if (tid == 0) {
#pragma unroll
        for (int s = 0; s < 3; s++) { MBAR_INIT(mbase + 8 * s, 1); MBAR_INIT(mbase + 8 * (3 + s), 16); }
    }
    __syncthreads();

    float acc[2][4][4];
#pragma unroll
    for (int i = 0; i < 2; i++)
#pragma unroll
        for (int j = 0; j < 4; j++)
#pragma unroll
            for (int k = 0; k < 4; k++) acc[i][j][k] = 0.0f;

    mma_mainloop_tma<2, 1, 32768, 3>(
        g_xT + (size_t)bm * 8 * 32768, g_WihT + (size_t)bn * 8 * 32768, 8,
        sbase, mbase, acc);

#pragma unroll
    for (int mi = 0; mi < 2; mi++) {
#pragma unroll
        for (int nf = 0; nf < 4; nf++) {
            int m = bm * 128 + wm + mi * 16 + lane / 4;   // token
            int n = bn * 128 + wn + nf * 8 + 2 * (lane & 3);
            float2 b2 = *reinterpret_cast<const float2*>(&g_bias_r[n]);
            int t0 = m % TT, b0 = m / TT;
            int m8 = m + 8;
            int t1 = m8 % TT, b1 = m8 / TT;
            size_t o0 = ((((size_t)t0 * 4 + (b0 >> 6)) * 32 + (n >> 7)) * 8192) + (b0 & 63) * 128 + (n & 127);
            size_t o1 = ((((size_t)t1 * 4 + (b1 >> 6)) * 32 + (n >> 7)) * 8192) + (b1 & 63) * 128 + (n & 127);
            *reinterpret_cast<float2*>(&g_xg[o0]) =
                make_float2(acc[mi][nf][0] + b2.x, acc[mi][nf][1] + b2.y);
            *reinterpret_cast<float2*>(&g_xg[o1]) =
                make_float2(acc[mi][nf][2] + b2.x, acc[mi][nf][3] + b2.y);
        }
    }
}

// ---------------- fused LSTM step ----------------
// KG=2, MF=2, ABYTES=16384, KC=16, S=4; grid (32,4)=128 CTAs, 512 threads.
// smem: 4*48KB stages + 32KB xg + 128 mbar = 229504 (< 232448 limit)
#define STEP_STAGE   (16384 + 32768)
#define STEP_XG_OFF  (4 * STEP_STAGE)
#define STEP_MB_OFF  (STEP_XG_OFF + 32768)
#define STEP_SMEM    (STEP_MB_OFF + 128)

__global__ __launch_bounds__(512, 1)
void lstm_step_mma(int t, int buf) {
    extern __shared__ __align__(1024) char smem[];
    const uint32_t sbase = smem_u32(smem);
    const uint32_t mbase = sbase + STEP_MB_OFF;
    const int bn = blockIdx.x, bm = blockIdx.y;
    const int tid = threadIdx.x, lane = tid & 31, wid = tid >> 5;

    if (tid == 0) {
#pragma unroll
        for (int s = 0; s < 4; s++) { MBAR_INIT(mbase + 8 * s, 1); MBAR_INIT(mbase + 8 * (4 + s), 16); }
        MBAR_INIT(mbase + 64, 1);
    }
    __syncthreads();
    // xg tile bulk (own barrier, parity 0)
    if (tid == 0) {
        MBAR_EXPECT_TX(mbase + 64, 32768u);
        bulk_g2s(sbase + STEP_XG_OFF,
                 (const char*)g_xg + (((size_t)t * 4 + bm) * 32 + bn) * 32768,
                 32768u, mbase + 64);
    }

    float acc[2][4][4];
#pragma unroll
    for (int i = 0; i < 2; i++)
#pragma unroll
        for (int j = 0; j < 4; j++)
#pragma unroll
            for (int k = 0; k < 4; k++) acc[i][j][k] = 0.0f;

    mma_mainloop_tma<2, 2, 16384, 4>(
        g_hT[buf] + (size_t)bm * 16 * 16384, g_WhhT + (size_t)bn * 16 * 32768, 16,
        sbase, mbase, acc);

    // stage both K-groups' partial gates in smem: gsm[2][64][128]
    float* gsm = reinterpret_cast<float*>(smem);
    {
        const int kg = wid >> 3, w8 = wid & 7;
        const int wm = (w8 >> 2) * 32, wn = (w8 & 3) * 32;
#pragma unroll
        for (int mi = 0; mi < 2; mi++) {
#pragma unroll
            for (int nf = 0; nf < 4; nf++) {
                int r0 = wm + mi * 16 + lane / 4;
                int col = wn + nf * 8 + 2 * (lane & 3);
                *reinterpret_cast<float2*>(&gsm[kg * 8192 + r0 * 128 + col]) =
                    make_float2(acc[mi][nf][0], acc[mi][nf][1]);
                *reinterpret_cast<float2*>(&gsm[kg * 8192 + (r0 + 8) * 128 + col]) =
                    make_float2(acc[mi][nf][2], acc[mi][nf][3]);
            }
        }
    }
    MBAR_WAIT(mbase + 64, 0u);
    __syncthreads();

    const float* xgsm = reinterpret_cast<const float*>(smem + STEP_XG_OFF);
    char* hout = g_hT[buf ^ 1];
#pragma unroll
    for (int it = 0; it < 4; it++) {
        int idx = it * 512 + tid;
        int m = idx >> 5, q = idx & 31;
        int mg = bm * 64 + m;
        int qg = bn * 32 + q;
        float4 g0 = *reinterpret_cast<const float4*>(&gsm[m * 128 + q * 4]);
        float4 g1 = *reinterpret_cast<const float4*>(&gsm[8192 + m * 128 + q * 4]);
        float4 xv = *reinterpret_cast<const float4*>(&xgsm[m * 128 + q * 4]);
        float a0 = g0.x + g1.x + xv.x;
        float a1 = g0.y + g1.y + xv.y;
        float a2 = g0.z + g1.z + xv.z;
        float a3 = g0.w + g1.w + xv.w;
        float ig = 1.0f / (1.0f + expf(-a0));
        float fg = 1.0f / (1.0f + expf(-a1));
        float gg = tanhf(a2);
        float og = 1.0f / (1.0f + expf(-a3));
        float cn = fg * g_cbuf[mg * HH + qg] + ig * gg;
        g_cbuf[mg * HH + qg] = cn;
        float hv = og * tanhf(cn);
        g_hlast[mg * HH + qg] = hv;
        bf16 hib = __float2bfloat16(hv);
        bf16 lob = __float2bfloat16(hv - __bfloat162float(hib));
        char* base = hout + ((size_t)(bm * 16 + (qg >> 6))) * 16384;
        uint32_t so = tile_off(m, qg & 63);
        *(bf16*)(base + so) = hib;
        *(bf16*)(base + 8192 + so) = lob;
    }
}

// ---------------- fp32 SIMT GEMM (head only) ----------------
#define EPI_BIAS 0
#define EPI_RELU 1
template <int BM, int BN, int BK, int TM, int TN, int EPI>
__global__ void gemm_bias_kernel(const float* __restrict__ A,
                                 const float* __restrict__ B,
                                 const float* __restrict__ bias,
                                 float* __restrict__ C,
                                 int M, int N, int K) {
    constexpr int NT = (BM * BN) / (TM * TN);
    __shared__ float As[BK][BM];
    __shared__ float Bs[BK][BN];
    const int tid = threadIdx.x;
    const int bn = blockIdx.x, bm = blockIdx.y;
    const int tx = tid % (BN / TN);
    const int ty = tid / (BN / TN);
    const float* Ab = A + (size_t)bm * BM * K;
    const float* Bb = B + (size_t)bn * BN * K;
    float acc[TM][TN];
#pragma unroll
    for (int i = 0; i < TM; i++)
#pragma unroll
        for (int j = 0; j < TN; j++) acc[i][j] = 0.0f;
    for (int k0 = 0; k0 < K; k0 += BK) {
        constexpr int A4 = BM * BK / 4;
        constexpr int B4 = BN * BK / 4;
#pragma unroll
        for (int i0 = 0; i0 < A4; i0 += NT) {
            int i = i0 + tid;
            int r = i / (BK / 4), c = (i % (BK / 4)) * 4;
            float4 v = *reinterpret_cast<const float4*>(Ab + (size_t)r * K + k0 + c);
            As[c + 0][r] = v.x; As[c + 1][r] = v.y; As[c + 2][r] = v.z; As[c + 3][r] = v.w;
        }
#pragma unroll
        for (int i0 = 0; i0 < B4; i0 += NT) {
            int i = i0 + tid;
            int r = i / (BK / 4), c = (i % (BK / 4)) * 4;
            float4 v = *reinterpret_cast<const float4*>(Bb + (size_t)r * K + k0 + c);
            Bs[c + 0][r] = v.x; Bs[c + 1][r] = v.y; Bs[c + 2][r] = v.z; Bs[c + 3][r] = v.w;
        }
        __syncthreads();
#pragma unroll
        for (int k = 0; k < BK; k++) {
            float ra[TM], rb[TN];
#pragma unroll
            for (int i = 0; i < TM; i += 4) {
                float4 v = *reinterpret_cast<const float4*>(&As[k][ty * TM + i]);
                ra[i] = v.x; ra[i + 1] = v.y; ra[i + 2] = v.z; ra[i + 3] = v.w;
            }
#pragma unroll
            for (int j = 0; j < TN; j += 4) {
                float4 v = *reinterpret_cast<const float4*>(&Bs[k][tx * TN + j]);
                rb[j] = v.x; rb[j + 1] = v.y; rb[j + 2] = v.z; rb[j + 3] = v.w;
            }
#pragma unroll
            for (int i = 0; i < TM; i++)
#pragma unroll
                for (int j = 0; j < TN; j++) acc[i][j] += ra[i] * rb[j];
        }
        __syncthreads();
    }
#pragma unroll
    for (int i = 0; i < TM; i++) {
        int m = bm * BM + ty * TM + i;
#pragma unroll
        for (int j = 0; j < TN; j++) {
            int n = bn * BN + tx * TN + j;
            float v = acc[i][j] + bias[n];
            if (EPI == EPI_RELU) v = fmaxf(v, 0.0f);
            C[(size_t)m * N + n] = v;
        }
    }
}

// ---------------- host ----------------
extern "C" void kernel_launch(void* const* d_in, const int* in_sizes, int n_in,
                              void* d_out, int out_size) {
    const float* x    = (const float*)d_in[0];
    const float* W_ih = (const float*)d_in[1];
    const float* W_hh = (const float*)d_in[2];
    const float* b_ih = (const float*)d_in[3];
    const float* b_hh = (const float*)d_in[4];
    const float* W1   = (const float*)d_in[5];
    const float* b1   = (const float*)d_in[6];
    const float* W2   = (const float*)d_in[7];
    const float* b2   = (const float*)d_in[8];
    float* out = (float*)d_out;

    float* p_hlast;
    cudaGetSymbolAddress((void**)&p_hlast, g_hlast);

    static int attr_set = 0;
    if (!attr_set) {
        cudaFuncSetAttribute(lstm_step_mma, cudaFuncAttributeMaxDynamicSharedMemorySize, STEP_SMEM);
        cudaFuncSetAttribute(xgates_mma_kernel, cudaFuncAttributeMaxDynamicSharedMemorySize, XG_SMEM);
        attr_set = 1;
    }

    // 1) pre-swizzled tiles for W_ih / W_hh / x; bias; zero state
    prep_kernel<<<1024, 256>>>(x, W_ih, W_hh, b_ih, b_hh);

    // 2) x_gates via HMMA + bulk-async, written in xg tile blocks
    xgates_mma_kernel<<<dim3(GG / 128, (NB * TT) / 128), 512, XG_SMEM>>>();

    // 3) 128 recurrent steps
    for (int t = 0; t < TT; t++)
        lstm_step_mma<<<dim3(GG / 128, NB / 64), 512, STEP_SMEM>>>(t, t & 1);

    // 4) head (fp32 SIMT)
    float* pre_out = out + NB * OUTD;
    gemm_bias_kernel<64, 128, 16, 4, 8, EPI_RELU>
        <<<dim3(HH / 128, NB / 64), 256>>>(p_hlast, W1, b1, pre_out, NB, HH, HH);
    gemm_bias_kernel<64, 128, 16, 4, 8, EPI_BIAS>
        <<<dim3(OUTD / 128, NB / 64), 256>>>(pre_out, W2, b2, out, NB, OUTD, HH);
}